// round 1
// baseline (speedup 1.0000x reference)
#include <cuda_runtime.h>
#include <math.h>

// DTW 2048x2048, squared-difference cost, output sqrt(DTW[N-1][N-1]).
// Unified recurrence with virtual border: v[-1][-1]=0, v[-1][j>=0]=inf,
// v[i>=0][-1]=inf  =>  v[i][j] = (x[i]-y[j])^2 + min(up, left, diag)
// reproduces the reference's row-0 cumsum and col-0 "up-only" cases exactly.
//
// Schedule: thread-skewed systolic wavefront, single block (single SM).
//   - T=256 threads, each owns C=8 fixed columns [t*C, t*C+8).
//   - Rows streamed in chunks of R=4. At step s, thread t processes chunk
//     k = s - t (rows [4k, 4k+4)) if 0 <= k < 512.
//   - Up-row + diag carried in registers (prev[C]); the only cross-thread
//     traffic is the right-edge column (R floats/step) through a
//     double-buffered smem strip: write buf[s&1][t], read buf[(s-1)&1][t-1].
//   - One __syncthreads per step (767 steps total).

#define NT   256
#define NC   8            // columns per thread (NT*NC = 2048)
#define NR   4            // rows per step
#define LEN  2048
#define NK   (LEN / NR)   // 512 chunks
#define NS   (NT - 1 + NK)// 767 steps

__global__ __launch_bounds__(NT, 1)
void dtw_kernel(const float* __restrict__ x,
                const float* __restrict__ y,
                float* __restrict__ out)
{
    __shared__ float  xs[LEN];       // 8 KB
    __shared__ float4 buf[2][NT];    // 8 KB edge double-buffer

    const int   t   = threadIdx.x;
    const float INF = __int_as_float(0x7f800000);

    // Preload x into smem (covered by the first step's barrier).
    {
        const float4* x4  = reinterpret_cast<const float4*>(x);
        float4*       xs4 = reinterpret_cast<float4*>(xs);
        #pragma unroll
        for (int i = t; i < LEN / 4; i += NT) xs4[i] = x4[i];
    }

    // This thread's y columns -> registers (coalesced 32B/thread).
    float yc[NC];
    {
        const float4* y4 = reinterpret_cast<const float4*>(y + t * NC);
        float4 a = y4[0], b = y4[1];
        yc[0] = a.x; yc[1] = a.y; yc[2] = a.z; yc[3] = a.w;
        yc[4] = b.x; yc[5] = b.y; yc[6] = b.z; yc[7] = b.w;
    }

    // Row carry: prev[c] = v[r-1][t*NC + c], starts as virtual row -1 = inf.
    float prev[NC];
    #pragma unroll
    for (int c = 0; c < NC; c++) prev[c] = INF;

    // diag carry for column t*NC: boundary value at row r0-1.
    // Thread 0, first chunk: DTW[-1][-1] = 0. Everyone else: inf.
    float diag_edge = (t == 0) ? 0.0f : INF;

    float last_v = 0.0f;

    for (int s = 0; s < NS; s++) {
        __syncthreads();
        const int k = s - t;
        if (k >= 0 && k < NK) {
            // Left-boundary values for rows [4k, 4k+4): produced by thread
            // t-1 at step s-1 (same chunk k). Thread 0's boundary is inf.
            float e[NR];
            if (t == 0) {
                #pragma unroll
                for (int i = 0; i < NR; i++) e[i] = INF;
            } else {
                float4 ev = buf[(s - 1) & 1][t - 1];
                e[0] = ev.x; e[1] = ev.y; e[2] = ev.z; e[3] = ev.w;
            }

            const int r0 = k * NR;
            float4 xv = *reinterpret_cast<const float4*>(xs + r0);
            float  xr[NR] = {xv.x, xv.y, xv.z, xv.w};
            float  vout[NR];

            #pragma unroll
            for (int i = 0; i < NR; i++) {
                float left = e[i];
                float dg   = diag_edge;     // boundary at row r0+i-1
                const float xi = xr[i];
                #pragma unroll
                for (int c = 0; c < NC; c++) {
                    float d = xi - yc[c];
                    float m = fminf(fminf(prev[c], dg), left);
                    float v = fmaf(d, d, m);
                    dg      = prev[c];       // becomes diag for column c+1
                    prev[c] = v;
                    left    = v;
                }
                diag_edge = e[i];            // boundary row advances
                vout[i]   = left;            // right-edge value of this row
            }

            buf[s & 1][t] = make_float4(vout[0], vout[1], vout[2], vout[3]);
            last_v = vout[NR - 1];
        }
    }

    // Thread NT-1 holds the final cell v[2047][2047] after its last chunk.
    if (t == NT - 1) out[0] = sqrtf(last_v);
}

extern "C" void kernel_launch(void* const* d_in, const int* in_sizes, int n_in,
                              void* d_out, int out_size)
{
    const float* x = (const float*)d_in[0];
    const float* y = (const float*)d_in[1];
    float* out = (float*)d_out;
    (void)in_sizes; (void)n_in; (void)out_size;
    dtw_kernel<<<1, NT>>>(x, y, out);
}

// round 2
// speedup vs baseline: 1.0002x; 1.0002x over previous
#include <cuda_runtime.h>
#include <math.h>

// DTW 2048x2048, squared-difference cost, output sqrt(DTW[N-1][N-1]).
// Unified recurrence with virtual border: v[-1][-1]=0, v[-1][j>=0]=inf,
// v[i>=0][-1]=inf  =>  v[i][j] = (x[i]-y[j])^2 + min(up, left, diag)
// reproduces the reference's row-0 cumsum and col-0 "up-only" cases exactly.
//
// Schedule: thread-skewed systolic wavefront, single block (single SM).
//   - T=256 threads, each owns C=8 fixed columns [t*C, t*C+8).
//   - Rows streamed in chunks of R=4. At step s, thread t processes chunk
//     k = s - t (rows [4k, 4k+4)) if 0 <= k < 512.
//   - Up-row + diag carried in registers (prev[C]); the only cross-thread
//     traffic is the right-edge column (R floats/step) through a
//     double-buffered smem strip: write buf[s&1][t], read buf[(s-1)&1][t-1].
//   - One __syncthreads per step (767 steps total).

#define NT   256
#define NC   8            // columns per thread (NT*NC = 2048)
#define NR   4            // rows per step
#define LEN  2048
#define NK   (LEN / NR)   // 512 chunks
#define NS   (NT - 1 + NK)// 767 steps

__global__ __launch_bounds__(NT, 1)
void dtw_kernel(const float* __restrict__ x,
                const float* __restrict__ y,
                float* __restrict__ out)
{
    __shared__ float  xs[LEN];       // 8 KB
    __shared__ float4 buf[2][NT];    // 8 KB edge double-buffer

    const int   t   = threadIdx.x;
    const float INF = __int_as_float(0x7f800000);

    // Preload x into smem (covered by the first step's barrier).
    {
        const float4* x4  = reinterpret_cast<const float4*>(x);
        float4*       xs4 = reinterpret_cast<float4*>(xs);
        #pragma unroll
        for (int i = t; i < LEN / 4; i += NT) xs4[i] = x4[i];
    }

    // This thread's y columns -> registers (coalesced 32B/thread).
    float yc[NC];
    {
        const float4* y4 = reinterpret_cast<const float4*>(y + t * NC);
        float4 a = y4[0], b = y4[1];
        yc[0] = a.x; yc[1] = a.y; yc[2] = a.z; yc[3] = a.w;
        yc[4] = b.x; yc[5] = b.y; yc[6] = b.z; yc[7] = b.w;
    }

    // Row carry: prev[c] = v[r-1][t*NC + c], starts as virtual row -1 = inf.
    float prev[NC];
    #pragma unroll
    for (int c = 0; c < NC; c++) prev[c] = INF;

    // diag carry for column t*NC: boundary value at row r0-1.
    // Thread 0, first chunk: DTW[-1][-1] = 0. Everyone else: inf.
    float diag_edge = (t == 0) ? 0.0f : INF;

    float last_v = 0.0f;

    for (int s = 0; s < NS; s++) {
        __syncthreads();
        const int k = s - t;
        if (k >= 0 && k < NK) {
            // Left-boundary values for rows [4k, 4k+4): produced by thread
            // t-1 at step s-1 (same chunk k). Thread 0's boundary is inf.
            float e[NR];
            if (t == 0) {
                #pragma unroll
                for (int i = 0; i < NR; i++) e[i] = INF;
            } else {
                float4 ev = buf[(s - 1) & 1][t - 1];
                e[0] = ev.x; e[1] = ev.y; e[2] = ev.z; e[3] = ev.w;
            }

            const int r0 = k * NR;
            float4 xv = *reinterpret_cast<const float4*>(xs + r0);
            float  xr[NR] = {xv.x, xv.y, xv.z, xv.w};
            float  vout[NR];

            #pragma unroll
            for (int i = 0; i < NR; i++) {
                float left = e[i];
                float dg   = diag_edge;     // boundary at row r0+i-1
                const float xi = xr[i];
                #pragma unroll
                for (int c = 0; c < NC; c++) {
                    float d = xi - yc[c];
                    float m = fminf(fminf(prev[c], dg), left);
                    float v = fmaf(d, d, m);
                    dg      = prev[c];       // becomes diag for column c+1
                    prev[c] = v;
                    left    = v;
                }
                diag_edge = e[i];            // boundary row advances
                vout[i]   = left;            // right-edge value of this row
            }

            buf[s & 1][t] = make_float4(vout[0], vout[1], vout[2], vout[3]);
            last_v = vout[NR - 1];
        }
    }

    // Thread NT-1 holds the final cell v[2047][2047] after its last chunk.
    if (t == NT - 1) out[0] = sqrtf(last_v);
}

extern "C" void kernel_launch(void* const* d_in, const int* in_sizes, int n_in,
                              void* d_out, int out_size)
{
    const float* x = (const float*)d_in[0];
    const float* y = (const float*)d_in[1];
    float* out = (float*)d_out;
    (void)in_sizes; (void)n_in; (void)out_size;
    dtw_kernel<<<1, NT>>>(x, y, out);
}